// round 1
// baseline (speedup 1.0000x reference)
#include <cuda_runtime.h>

#define DM 2048
#define NB 32
#define NT 8
#define NH 32
#define DH 64
#define CT 1016
#define SEQ 1024
#define MROWS 256   // NB*NT

// ---------------- scratch (device globals; no allocation allowed) ----------------
__device__ float g_q   [NB*NH*NT*DH];   // [b][h][t][d]
__device__ float g_kn  [NB*NH*NT*DH];   // new K
__device__ float g_vn  [NB*NH*NT*DH];   // new V
__device__ float g_attn[MROWS*DM];      // [b*8+t][h*64+d]

// ---------------- cp.async helpers ----------------
__device__ __forceinline__ void cp16(unsigned dst, const void* src) {
    asm volatile("cp.async.cg.shared.global [%0], [%1], 16;\n" :: "r"(dst), "l"(src));
}
__device__ __forceinline__ void cp_commit() {
    asm volatile("cp.async.commit_group;\n");
}
__device__ __forceinline__ void cp_wait1() {
    asm volatile("cp.async.wait_group 1;\n");
}
__device__ __forceinline__ void cp_wait0() {
    asm volatile("cp.async.wait_group 0;\n");
}

// =================================================================================
// Kernel 1: fused QKV projection.  Y[256,6144] = X[256,2048] @ [Wq;Wk;Wv]^T + bias
// Block tile 64x64, BK=16, 256 threads, 4x4 per-thread microtile.
// grid = (4 row-tiles, 96 col-tiles)  (col-tiles grouped so W stays L2-hot)
// =================================================================================
__global__ __launch_bounds__(256) void qkv_kernel(
    const float* __restrict__ x,
    const float* __restrict__ Wq, const float* __restrict__ bq,
    const float* __restrict__ Wk, const float* __restrict__ bk,
    const float* __restrict__ Wv, const float* __restrict__ bv)
{
    __shared__ float As[16][64];
    __shared__ float Bs[16][64];
    const int tid  = threadIdx.x;
    const int byr  = blockIdx.x;       // row tile 0..3
    const int bxc  = blockIdx.y;       // col tile 0..95
    const int type = bxc >> 5;         // 0=q 1=k 2=v
    const int ct   = bxc & 31;         // head index (64-wide tiles == one head)

    const float* W   = (type == 0) ? Wq : (type == 1) ? Wk : Wv;
    const float* bia = (type == 0) ? bq : (type == 1) ? bk : bv;
    float*       dst = (type == 0) ? g_q : (type == 1) ? g_kn : g_vn;

    const int tx = tid & 15;           // n microtile
    const int ty = tid >> 4;           // m microtile
    const int lr = tid >> 2;           // staging row 0..63
    const int lc = (tid & 3) << 2;     // staging k-col {0,4,8,12}

    const float* xrow = x + (size_t)(byr * 64 + lr) * DM;
    const float* wrow = W + (size_t)(ct  * 64 + lr) * DM;

    float acc[4][4];
#pragma unroll
    for (int i = 0; i < 4; i++)
#pragma unroll
        for (int j = 0; j < 4; j++) acc[i][j] = 0.f;

    float4 ra = *(const float4*)(xrow + lc);
    float4 rb = *(const float4*)(wrow + lc);
    {
        const float* pa = (const float*)&ra;
        const float* pb = (const float*)&rb;
#pragma unroll
        for (int j = 0; j < 4; j++) { As[lc + j][lr] = pa[j]; Bs[lc + j][lr] = pb[j]; }
    }
    __syncthreads();

    for (int kt = 0; kt < DM / 16; kt++) {
        const int nk = (kt + 1) * 16;
        if (nk < DM) {
            ra = *(const float4*)(xrow + nk + lc);
            rb = *(const float4*)(wrow + nk + lc);
        }
#pragma unroll
        for (int k = 0; k < 16; k++) {
            float4 a4 = *(const float4*)&As[k][ty << 2];
            float4 b4 = *(const float4*)&Bs[k][tx << 2];
            float av[4] = {a4.x, a4.y, a4.z, a4.w};
            float bw[4] = {b4.x, b4.y, b4.z, b4.w};
#pragma unroll
            for (int i = 0; i < 4; i++)
#pragma unroll
                for (int j = 0; j < 4; j++) acc[i][j] += av[i] * bw[j];
        }
        __syncthreads();
        if (nk < DM) {
            const float* pa = (const float*)&ra;
            const float* pb = (const float*)&rb;
#pragma unroll
            for (int j = 0; j < 4; j++) { As[lc + j][lr] = pa[j]; Bs[lc + j][lr] = pb[j]; }
            __syncthreads();
        }
    }

    // epilogue: scatter into [b][h][t][d]
#pragma unroll
    for (int i = 0; i < 4; i++) {
        const int m = byr * 64 + (ty << 2) + i;
        const int b = m >> 3, t = m & 7;
#pragma unroll
        for (int j = 0; j < 4; j++) {
            const int d = (tx << 2) + j;
            dst[(((size_t)(b * NH + ct) * NT + t) * DH) + d] = acc[i][j] + bia[ct * 64 + d];
        }
    }
}

// =================================================================================
// Kernel 2: attention per (b,h).  1024 blocks x 256 threads.
// smem: q[8*64] | p[8*1024] | kv[2][64*68] | inv_sum[8]   = 69664 B dynamic
// Pass1: stream K (cache + new) in 64-row cp.async tiles -> scores
// softmax (exact), Pass2: stream V -> out accum, cross-warp reduce.
// =================================================================================
#define KV_ROW 68                      // 64 + 4 pad floats (conflict-free, 16B aligned)
#define KV_TILE (64 * KV_ROW)
#define ATTN_SMEM_FLOATS (512 + 8192 + 2 * KV_TILE + 8)

__device__ __forceinline__ void stage_tile(unsigned kv_smem_addr, int buf, int tile, int tid,
                                           const float* __restrict__ cache,
                                           const float* __restrict__ newer)
{
#pragma unroll
    for (int i = 0; i < 4; i++) {
        const int idx = tid + i * 256;           // 0..1023
        const int sl  = idx >> 4;                // row in tile 0..63
        const int c4  = idx & 15;                // float4 col 0..15
        const int s   = tile * 64 + sl;          // global seq position
        const float* src = (s < CT) ? (cache + (size_t)s * DH + c4 * 4)
                                    : (newer + (size_t)(s - CT) * DH + c4 * 4);
        const unsigned dstoff = (unsigned)((buf * KV_TILE + sl * KV_ROW + c4 * 4) * 4);
        cp16(kv_smem_addr + dstoff, src);
    }
    cp_commit();
}

__global__ __launch_bounds__(256) void attn_kernel(
    const float* __restrict__ cache_k,
    const float* __restrict__ cache_v)
{
    extern __shared__ float sm[];
    float* q_s     = sm;                 // 512
    float* p       = sm + 512;           // 8192
    float* kv      = p + 8192;           // 2*KV_TILE
    float* inv_sum = kv + 2 * KV_TILE;   // 8

    const int tid = threadIdx.x;
    const int w   = tid >> 5;
    const int l   = tid & 31;
    const int bh  = blockIdx.x;
    const int b   = bh >> 5;
    const int h   = bh & 31;

    // q (scaled by 1/sqrt(64) = 0.125)
    const float* qsrc = g_q + (size_t)bh * (NT * DH);
    q_s[tid]       = qsrc[tid]       * 0.125f;
    q_s[tid + 256] = qsrc[tid + 256] * 0.125f;

    const float* ck = cache_k + (size_t)bh * CT * DH;
    const float* cv = cache_v + (size_t)bh * CT * DH;
    const float* kn = g_kn + (size_t)bh * (NT * DH);
    const float* vn = g_vn + (size_t)bh * (NT * DH);

    const unsigned kv_addr = (unsigned)__cvta_generic_to_shared(kv);

    // ---------------- Pass 1: scores = q @ K^T ----------------
    stage_tile(kv_addr, 0, 0, tid, ck, kn);
    for (int c = 0; c < 16; c++) {
        if (c < 15) { stage_tile(kv_addr, (c + 1) & 1, c + 1, tid, ck, kn); cp_wait1(); }
        else        { cp_wait0(); }
        __syncthreads();               // tile c visible to all (also covers q_s on c==0)

        const float* kb = kv + (c & 1) * KV_TILE;
        const int g  = tid >> 6;       // t-pair group 0..3
        const int sl = tid & 63;       // row within tile
        const int t0 = g * 2, t1 = g * 2 + 1;
        float a0 = 0.f, a1 = 0.f;
        const float4* krow = (const float4*)(kb + sl * KV_ROW);
        const float4* q0   = (const float4*)(q_s + t0 * DH);
        const float4* q1   = (const float4*)(q_s + t1 * DH);
#pragma unroll
        for (int c4 = 0; c4 < 16; c4++) {
            float4 kk = krow[c4];
            float4 qa = q0[c4], qb = q1[c4];
            a0 += kk.x * qa.x + kk.y * qa.y + kk.z * qa.z + kk.w * qa.w;
            a1 += kk.x * qb.x + kk.y * qb.y + kk.z * qb.z + kk.w * qb.w;
        }
        const int s = c * 64 + sl;
        p[t0 * SEQ + s] = a0;
        p[t1 * SEQ + s] = a1;
        __syncthreads();               // buffer reusable next-next iter
    }

    // prefetch first V tile (buf0 is free: last K compute used buf1)
    stage_tile(kv_addr, 0, 0, tid, cv, vn);

    // ---------------- softmax: warp w owns row t=w ----------------
    {
        float* pr = p + w * SEQ;
        float mx = -1e30f;
        for (int i = l; i < SEQ; i += 32) mx = fmaxf(mx, pr[i]);
#pragma unroll
        for (int o = 16; o; o >>= 1) mx = fmaxf(mx, __shfl_xor_sync(0xffffffffu, mx, o));
        float sum = 0.f;
        for (int i = l; i < SEQ; i += 32) {
            float e = __expf(pr[i] - mx);
            pr[i] = e;
            sum += e;
        }
#pragma unroll
        for (int o = 16; o; o >>= 1) sum += __shfl_xor_sync(0xffffffffu, sum, o);
        if (l == 0) inv_sum[w] = 1.0f / sum;
    }
    __syncthreads();

    // ---------------- Pass 2: out = p @ V ----------------
    float acc[8][2];
#pragma unroll
    for (int t = 0; t < 8; t++) { acc[t][0] = 0.f; acc[t][1] = 0.f; }

    for (int c = 0; c < 16; c++) {
        if (c < 15) { stage_tile(kv_addr, (c + 1) & 1, c + 1, tid, cv, vn); cp_wait1(); }
        else        { cp_wait0(); }
        __syncthreads();

        const float* vb = kv + (c & 1) * KV_TILE;
#pragma unroll
        for (int r = 0; r < 8; r++) {
            const int sl = w * 8 + r;                 // warp-private row range
            const float v0 = vb[sl * KV_ROW + l];
            const float v1 = vb[sl * KV_ROW + 32 + l];
            const int s = c * 64 + sl;
#pragma unroll
            for (int t = 0; t < 8; t++) {
                const float pw = p[t * SEQ + s];      // broadcast
                acc[t][0] += pw * v0;
                acc[t][1] += pw * v1;
            }
        }
        __syncthreads();
    }

    // ---------------- cross-warp reduce (reuse p as scratch) ----------------
    float* red = p;                                   // need 8*512 = 4096 floats
#pragma unroll
    for (int t = 0; t < 8; t++) {
        red[w * 512 + t * 64 + l]      = acc[t][0];
        red[w * 512 + t * 64 + 32 + l] = acc[t][1];
    }
    __syncthreads();
    for (int i = tid; i < 512; i += 256) {
        float ssum = 0.f;
#pragma unroll
        for (int ww = 0; ww < 8; ww++) ssum += red[ww * 512 + i];
        const int t = i >> 6, d = i & 63;
        g_attn[(size_t)(b * NT + t) * DM + h * DH + d] = ssum * inv_sum[t];
    }
}

// =================================================================================
// Kernel 3: output projection.  out[256,2048] = g_attn @ Wo^T + bo
// =================================================================================
__global__ __launch_bounds__(256) void oproj_kernel(
    const float* __restrict__ Wo, const float* __restrict__ bo,
    float* __restrict__ out)
{
    __shared__ float As[16][64];
    __shared__ float Bs[16][64];
    const int tid = threadIdx.x;
    const int byr = blockIdx.x;        // 0..3
    const int bxc = blockIdx.y;        // 0..31

    const int tx = tid & 15;
    const int ty = tid >> 4;
    const int lr = tid >> 2;
    const int lc = (tid & 3) << 2;

    const float* arow = g_attn + (size_t)(byr * 64 + lr) * DM;
    const float* wrow = Wo     + (size_t)(bxc * 64 + lr) * DM;

    float acc[4][4];
#pragma unroll
    for (int i = 0; i < 4; i++)
#pragma unroll
        for (int j = 0; j < 4; j++) acc[i][j] = 0.f;

    float4 ra = *(const float4*)(arow + lc);
    float4 rb = *(const float4*)(wrow + lc);
    {
        const float* pa = (const float*)&ra;
        const float* pb = (const float*)&rb;
#pragma unroll
        for (int j = 0; j < 4; j++) { As[lc + j][lr] = pa[j]; Bs[lc + j][lr] = pb[j]; }
    }
    __syncthreads();

    for (int kt = 0; kt < DM / 16; kt++) {
        const int nk = (kt + 1) * 16;
        if (nk < DM) {
            ra = *(const float4*)(arow + nk + lc);
            rb = *(const float4*)(wrow + nk + lc);
        }
#pragma unroll
        for (int k = 0; k < 16; k++) {
            float4 a4 = *(const float4*)&As[k][ty << 2];
            float4 b4 = *(const float4*)&Bs[k][tx << 2];
            float av[4] = {a4.x, a4.y, a4.z, a4.w};
            float bw[4] = {b4.x, b4.y, b4.z, b4.w};
#pragma unroll
            for (int i = 0; i < 4; i++)
#pragma unroll
                for (int j = 0; j < 4; j++) acc[i][j] += av[i] * bw[j];
        }
        __syncthreads();
        if (nk < DM) {
            const float* pa = (const float*)&ra;
            const float* pb = (const float*)&rb;
#pragma unroll
            for (int j = 0; j < 4; j++) { As[lc + j][lr] = pa[j]; Bs[lc + j][lr] = pb[j]; }
            __syncthreads();
        }
    }

#pragma unroll
    for (int i = 0; i < 4; i++) {
        const int m = byr * 64 + (ty << 2) + i;
#pragma unroll
        for (int j = 0; j < 4; j++) {
            const int n = bxc * 64 + (tx << 2) + j;
            out[(size_t)m * DM + n] = acc[i][j] + bo[n];
        }
    }
}

// =================================================================================
// launch
// =================================================================================
extern "C" void kernel_launch(void* const* d_in, const int* in_sizes, int n_in,
                              void* d_out, int out_size)
{
    const float* x        = (const float*)d_in[0];
    const float* cache_k  = (const float*)d_in[1];
    const float* cache_v  = (const float*)d_in[2];
    const float* Wq       = (const float*)d_in[3];
    const float* bq       = (const float*)d_in[4];
    const float* Wk       = (const float*)d_in[5];
    const float* bk       = (const float*)d_in[6];
    const float* Wv       = (const float*)d_in[7];
    const float* bv       = (const float*)d_in[8];
    const float* Wo       = (const float*)d_in[9];
    const float* bo       = (const float*)d_in[10];
    float*       out      = (float*)d_out;

    static const size_t attn_smem = (size_t)ATTN_SMEM_FLOATS * sizeof(float);
    cudaFuncSetAttribute(attn_kernel, cudaFuncAttributeMaxDynamicSharedMemorySize,
                         (int)attn_smem);

    dim3 gq(4, 96);
    qkv_kernel<<<gq, 256>>>(x, Wq, bq, Wk, bk, Wv, bv);

    attn_kernel<<<NB * NH, 256, attn_smem>>>(cache_k, cache_v);

    dim3 go(4, 32);
    oproj_kernel<<<go, 256>>>(Wo, bo, out);
}